// round 2
// baseline (speedup 1.0000x reference)
#include <cuda_runtime.h>

// SelfNorm collapsed: out = x*std_w + mean*(mean_w - std_w), per (b,c) row.
// One WARP per row: no smem, no __syncthreads. Pass 1 reads row from DRAM
// (accumulate stats, discard data); pass 2 re-reads (L2-resident) and writes.

#define HW 3136          // 56*56
#define F4 784           // HW/4  = 24*32 + 16
#define NTHREADS 256
#define WARPS_PER_CTA 8
#define EPS 1e-5f

__device__ __forceinline__ float tiny_mlp(float mean, float std,
                                          const float* __restrict__ W1,
                                          const float* __restrict__ b1,
                                          const float* __restrict__ W2,
                                          const float* __restrict__ b2) {
    float z = __ldg(b2);
    #pragma unroll
    for (int o = 0; o < 16; o++) {
        float h = fmaf(__ldg(W1 + 2 * o), mean,
                  fmaf(__ldg(W1 + 2 * o + 1), std, __ldg(b1 + o)));
        h = fmaxf(h, 0.0f);
        z = fmaf(__ldg(W2 + o), h, z);
    }
    return 1.0f / (1.0f + __expf(-z));
}

__global__ void __launch_bounds__(NTHREADS)
selfnorm_kernel(const float4* __restrict__ x,
                const float* __restrict__ W1m, const float* __restrict__ b1m,
                const float* __restrict__ W2m, const float* __restrict__ b2m,
                const float* __restrict__ W1s, const float* __restrict__ b1s,
                const float* __restrict__ W2s, const float* __restrict__ b2s,
                float4* __restrict__ out) {
    const int lane = threadIdx.x & 31;
    const int row  = blockIdx.x * WARPS_PER_CTA + (threadIdx.x >> 5);

    const float4* __restrict__ xr   = x   + (size_t)row * F4;
    float4*       __restrict__ orow = out + (size_t)row * F4;

    // ---- Pass 1: stats (data discarded) ----
    float s = 0.0f, sq = 0.0f;
    #pragma unroll 8
    for (int i = 0; i < 24; i++) {
        float4 a = xr[lane + 32 * i];
        s += a.x + a.y + a.z + a.w;
        sq = fmaf(a.x, a.x, sq);
        sq = fmaf(a.y, a.y, sq);
        sq = fmaf(a.z, a.z, sq);
        sq = fmaf(a.w, a.w, sq);
    }
    if (lane < 16) {                       // remainder: 784 - 24*32 = 16
        float4 a = xr[768 + lane];
        s += a.x + a.y + a.z + a.w;
        sq = fmaf(a.x, a.x, sq);
        sq = fmaf(a.y, a.y, sq);
        sq = fmaf(a.z, a.z, sq);
        sq = fmaf(a.w, a.w, sq);
    }

    // Butterfly reduce: every lane gets the full sums.
    #pragma unroll
    for (int o = 16; o > 0; o >>= 1) {
        s  += __shfl_xor_sync(0xffffffffu, s,  o);
        sq += __shfl_xor_sync(0xffffffffu, sq, o);
    }

    const float n = (float)HW;
    float mean = s / n;
    float var  = (sq - n * mean * mean) / (n - 1.0f);
    var = fmaxf(var, 0.0f);
    float std = sqrtf(var + EPS);

    // Every lane computes the MLPs redundantly (fma pipe has headroom).
    float mean_w = tiny_mlp(mean, std, W1m, b1m, W2m, b2m);
    float std_w  = tiny_mlp(mean, std, W1s, b1s, W2s, b2s);

    const float alpha = std_w;
    const float beta  = mean * (mean_w - std_w);

    // ---- Pass 2: re-read (L2-resident) + transform + store ----
    #pragma unroll 8
    for (int i = 0; i < 24; i++) {
        float4 a = xr[lane + 32 * i];
        float4 r;
        r.x = fmaf(a.x, alpha, beta);
        r.y = fmaf(a.y, alpha, beta);
        r.z = fmaf(a.z, alpha, beta);
        r.w = fmaf(a.w, alpha, beta);
        orow[lane + 32 * i] = r;
    }
    if (lane < 16) {
        float4 a = xr[768 + lane];
        float4 r;
        r.x = fmaf(a.x, alpha, beta);
        r.y = fmaf(a.y, alpha, beta);
        r.z = fmaf(a.z, alpha, beta);
        r.w = fmaf(a.w, alpha, beta);
        orow[768 + lane] = r;
    }
}

extern "C" void kernel_launch(void* const* d_in, const int* in_sizes, int n_in,
                              void* d_out, int out_size) {
    const float4* x  = (const float4*)d_in[0];
    const float* W1m = (const float*)d_in[1];
    const float* b1m = (const float*)d_in[2];
    const float* W2m = (const float*)d_in[3];
    const float* b2m = (const float*)d_in[4];
    const float* W1s = (const float*)d_in[5];
    const float* b1s = (const float*)d_in[6];
    const float* W2s = (const float*)d_in[7];
    const float* b2s = (const float*)d_in[8];
    float4* out = (float4*)d_out;

    const int rows = 32 * 256;                         // B * C = 8192
    selfnorm_kernel<<<rows / WARPS_PER_CTA, NTHREADS>>>(x, W1m, b1m, W2m, b2m,
                                                        W1s, b1s, W2s, b2s, out);
}